// round 6
// baseline (speedup 1.0000x reference)
#include <cuda_runtime.h>

#define BB 4
#define SS 256
#define DD 512
#define PP 256
#define TI 4    // query rows per score block

// Scratch (device globals — no allocation allowed)
__device__ float g_pq [BB*SS*PP];   // [b][i][p]
__device__ float g_pkT[BB*PP*SS];   // [b][p][j]

__device__ __forceinline__ float fast_tanh(float x) {
    float y; asm("tanh.approx.f32 %0, %1;" : "=f"(y) : "f"(x)); return y;
}

// ---------------------------------------------------------------------------
// Phase 1: pq = seq @ W2^T ([b][i][p]); pk = seq @ W1^T (transposed [b][p][j])
// 64x64 tile, K-chunk 16, 512 THREADS (16 warps -> 4/SMSP), 4x2 microtile,
// double-buffered smem + register prefetch. grid (4,16,2) = 128 CTAs (1 wave).
// ---------------------------------------------------------------------------
__global__ __launch_bounds__(512) void proj_kernel(
    const float* __restrict__ seq,
    const float* __restrict__ W1,
    const float* __restrict__ W2)
{
    __shared__ float As[2][16][68];
    __shared__ float Bs[2][16][68];
    const float* Wm = blockIdx.z ? W1 : W2;
    const int row0 = blockIdx.y * 64;
    const int col0 = blockIdx.x * 64;
    const int tid = threadIdx.x;
    const int tx = tid & 31;            // -> 2 N-cols
    const int ty = tid >> 5;            // -> 4 M-rows (constant per warp: A LDS = broadcast)
    const int lm  = tid >> 3;           // 0..63 tile row to load
    const int lk2 = (tid & 7) << 1;     // 0,2,..,14 k offset (float2)

    const float* ap = seq + (row0 + lm) * DD + lk2;
    const float* wp = Wm  + (col0 + lm) * DD + lk2;

    {   // prologue chunk 0
        float2 a = *(const float2*)ap;
        float2 w = *(const float2*)wp;
        As[0][lk2+0][lm] = a.x; As[0][lk2+1][lm] = a.y;
        Bs[0][lk2+0][lm] = w.x; Bs[0][lk2+1][lm] = w.y;
    }
    __syncthreads();

    float acc[4][2] = {};
    int buf = 0;

    for (int k0 = 0; k0 < DD; k0 += 16) {
        float2 an, wn;
        const bool has_next = (k0 + 16) < DD;
        if (has_next) {
            an = *(const float2*)(ap + k0 + 16);
            wn = *(const float2*)(wp + k0 + 16);
        }
        #pragma unroll
        for (int k = 0; k < 16; k++) {
            float4 av = *(const float4*)&As[buf][k][ty << 2];   // warp broadcast
            float2 bv = *(const float2*)&Bs[buf][k][tx << 1];
            float am[4] = {av.x, av.y, av.z, av.w};
            #pragma unroll
            for (int i = 0; i < 4; i++) {
                acc[i][0] = fmaf(am[i], bv.x, acc[i][0]);
                acc[i][1] = fmaf(am[i], bv.y, acc[i][1]);
            }
        }
        if (has_next) {
            const int nb = buf ^ 1;
            As[nb][lk2+0][lm] = an.x; As[nb][lk2+1][lm] = an.y;
            Bs[nb][lk2+0][lm] = wn.x; Bs[nb][lk2+1][lm] = wn.y;
            __syncthreads();
            buf = nb;
        }
    }

    #pragma unroll
    for (int i = 0; i < 4; i++) {
        int row = row0 + (ty << 2) + i;
        int col = col0 + (tx << 1);
        if (blockIdx.z == 0) {
            *(float2*)&g_pq[row * PP + col] = make_float2(acc[i][0], acc[i][1]);
        } else {
            int b = row >> 8, jj = row & 255;
            g_pkT[(b * PP + col + 0) * SS + jj] = acc[i][0];
            g_pkT[(b * PP + col + 1) * SS + jj] = acc[i][1];
        }
    }
}

// ---------------------------------------------------------------------------
// Phase 2: scores + softmax.  Block = (batch b, TI=4 query rows). 256 blocks.
// ---------------------------------------------------------------------------
__global__ __launch_bounds__(256) void score_kernel(
    const float* __restrict__ mask,
    const float* __restrict__ v,
    float* __restrict__ out_w)
{
    __shared__ float pq_s[TI][PP];
    __shared__ float v_s[PP];
    __shared__ float w_s[TI][SS];

    const int blk = blockIdx.x;
    const int b  = blk >> 6;                 // 64 tiles per batch
    const int i0 = (blk & 63) * TI;
    const int t  = threadIdx.x;

    v_s[t] = v[t];
    #pragma unroll
    for (int ii = 0; ii < TI; ii++)
        pq_s[ii][t] = g_pq[(b * SS + i0 + ii) * PP + t];
    __syncthreads();

    const float km = mask[b * SS + t];
    float acc[TI];
    #pragma unroll
    for (int ii = 0; ii < TI; ii++) acc[ii] = 0.f;

    const float* pkp = g_pkT + b * PP * SS + t;
    #pragma unroll 4
    for (int p = 0; p < PP; p++) {
        float pk = pkp[p * SS];              // coalesced, L2-resident
        float vv = v_s[p];
        #pragma unroll
        for (int ii = 0; ii < TI; ii++)
            acc[ii] = fmaf(vv, fast_tanh(pq_s[ii][p] + pk), acc[ii]);
    }
    #pragma unroll
    for (int ii = 0; ii < TI; ii++)
        w_s[ii][t] = (km > 0.f) ? acc[ii] : -1e9f;
    __syncthreads();

    // softmax: warp w (< TI) handles query row i0+w, 8 elems per lane
    const int wrp = t >> 5, lane = t & 31;
    if (wrp < TI) {
        float vals[8];
        float m = -3.4e38f;
        #pragma unroll
        for (int k = 0; k < 8; k++) { vals[k] = w_s[wrp][lane + 32*k]; m = fmaxf(m, vals[k]); }
        #pragma unroll
        for (int o = 16; o > 0; o >>= 1) m = fmaxf(m, __shfl_xor_sync(0xffffffffu, m, o));
        float sum = 0.f;
        #pragma unroll
        for (int k = 0; k < 8; k++) { vals[k] = __expf(vals[k] - m); sum += vals[k]; }
        #pragma unroll
        for (int o = 16; o > 0; o >>= 1) sum += __shfl_xor_sync(0xffffffffu, sum, o);
        const float qm  = mask[b * SS + i0 + wrp];
        const float inv = qm / sum;          // fold query-mask into weights
        float* orow = out_w + (b * SS + i0 + wrp) * SS;
        #pragma unroll
        for (int k = 0; k < 8; k++)
            orow[lane + 32*k] = vals[k] * inv;
    }
}

// ---------------------------------------------------------------------------
// Phase 3: attn = weights @ seq (batched GEMM). 64x64 tile, 512 threads,
// 4x2 microtile, double-buffered. grid (8,16) = 128 CTAs.
// ---------------------------------------------------------------------------
__global__ __launch_bounds__(512) void av_kernel(
    const float* __restrict__ w,      // [B*S, S]
    const float* __restrict__ seq,    // [B, S, D]
    float* __restrict__ out_attn)     // [B*S, D]
{
    __shared__ float As[2][16][68];   // As[buf][k][m]  (weights, transposed store)
    __shared__ float Bs[2][16][68];   // Bs[buf][k][n]  (seq, natural layout)
    const int row0 = blockIdx.y * 64;
    const int col0 = blockIdx.x * 64;
    const int b = row0 >> 8;
    const int tid = threadIdx.x;
    const int tx = tid & 31;
    const int ty = tid >> 5;
    const int lm  = tid >> 3;            // 0..63 (A load row)
    const int lk2 = (tid & 7) << 1;      // A load k offset (float2)
    const int kb  = tid >> 5;            // 0..15 (B load k row)
    const int nb  = (tid & 31) << 1;     // 0..62 (B load n col, float2)

    const float* ap = w + (row0 + lm) * SS + lk2;
    const float* sp = seq + b * SS * DD + kb * DD + col0 + nb;

    {
        float2 a = *(const float2*)ap;
        float2 s = *(const float2*)sp;
        As[0][lk2+0][lm] = a.x; As[0][lk2+1][lm] = a.y;
        *(float2*)&Bs[0][kb][nb] = s;
    }
    __syncthreads();

    float acc[4][2] = {};
    int buf = 0;

    for (int k0 = 0; k0 < SS; k0 += 16) {
        float2 an, sn;
        const bool has_next = (k0 + 16) < SS;
        if (has_next) {
            an = *(const float2*)(ap + k0 + 16);
            sn = *(const float2*)(sp + (k0 + 16) * DD);
        }
        #pragma unroll
        for (int k = 0; k < 16; k++) {
            float4 av = *(const float4*)&As[buf][k][ty << 2];   // warp broadcast
            float2 bv = *(const float2*)&Bs[buf][k][tx << 1];
            float am[4] = {av.x, av.y, av.z, av.w};
            #pragma unroll
            for (int i = 0; i < 4; i++) {
                acc[i][0] = fmaf(am[i], bv.x, acc[i][0]);
                acc[i][1] = fmaf(am[i], bv.y, acc[i][1]);
            }
        }
        if (has_next) {
            const int nbuf = buf ^ 1;
            As[nbuf][lk2+0][lm] = an.x; As[nbuf][lk2+1][lm] = an.y;
            *(float2*)&Bs[nbuf][kb][nb] = sn;
            __syncthreads();
            buf = nbuf;
        }
    }

    #pragma unroll
    for (int i = 0; i < 4; i++) {
        float* orow = out_attn + (row0 + (ty << 2) + i) * DD + col0 + (tx << 1);
        *(float2*)orow = make_float2(acc[i][0], acc[i][1]);
    }
}

extern "C" void kernel_launch(void* const* d_in, const int* in_sizes, int n_in,
                              void* d_out, int out_size)
{
    const float* seq  = (const float*)d_in[0];
    const float* mask = (const float*)d_in[1];
    const float* W1   = (const float*)d_in[2];
    const float* W2   = (const float*)d_in[3];
    const float* v    = (const float*)d_in[4];
    float* out_attn = (float*)d_out;                    // [B,S,D]
    float* out_w    = (float*)d_out + BB * SS * DD;     // [B,S,S]

    dim3 g1(PP / 64, (BB * SS) / 64, 2);
    proj_kernel<<<g1, 512>>>(seq, W1, W2);
    score_kernel<<<(BB * SS) / TI, 256>>>(mask, v, out_w);
    dim3 g3(DD / 64, (BB * SS) / 64);
    av_kernel<<<g3, 512>>>(out_w, seq, out_attn);
}

// round 7
// speedup vs baseline: 1.1815x; 1.1815x over previous
#include <cuda_runtime.h>

#define BB 4
#define SS 256
#define DD 512
#define PP 256
#define TI 4    // query rows per score block
#define PS 2    // p-split for score
#define KS 2    // K-split factor for proj

// Scratch (device globals — no allocation allowed)
__device__ float g_pq2 [KS][BB*SS*PP];   // pq partials  [ks][b][i][p]
__device__ float g_pkT2[KS][BB*PP*SS];   // pkT partials [ks][b][p][j]
__device__ float g_pkT [BB*PP*SS];       // combined     [b][p][j]
__device__ float g_spart[PS][BB*SS*SS];  // partial scores [ps][row][j]

__device__ __forceinline__ float fast_tanh(float x) {
    float y; asm("tanh.approx.f32 %0, %1;" : "=f"(y) : "f"(x)); return y;
}

// ---------------------------------------------------------------------------
// Phase 1: pq = seq @ W2^T ; pk = seq @ W1^T (transposed store), K-SPLIT x2.
// 256 CTAs, 256 thr, 64x64 tile, 4x4 microtile, double-buffered. (R5-proven)
// ---------------------------------------------------------------------------
__global__ __launch_bounds__(256, 2) void proj_kernel(
    const float* __restrict__ seq,
    const float* __restrict__ W1,
    const float* __restrict__ W2)
{
    __shared__ float As[2][16][68];
    __shared__ float Bs[2][16][68];
    const int zm = blockIdx.z & 1;          // 0 = pq(W2), 1 = pk(W1)
    const int ks = blockIdx.z >> 1;         // k-split index
    const float* Wm = zm ? W1 : W2;
    const int row0 = blockIdx.y * 64;
    const int col0 = blockIdx.x * 64;
    const int tid = threadIdx.x;
    const int tx = tid & 15, ty = tid >> 4;
    const int lm = tid >> 2;
    const int lk = (tid & 3) << 2;
    const int kbase = ks * (DD / KS);

    const float* ap = seq + (row0 + lm) * DD + kbase + lk;
    const float* wp = Wm  + (col0 + lm) * DD + kbase + lk;

    {
        float4 a = *(const float4*)ap;
        float4 w = *(const float4*)wp;
        As[0][lk+0][lm] = a.x; As[0][lk+1][lm] = a.y; As[0][lk+2][lm] = a.z; As[0][lk+3][lm] = a.w;
        Bs[0][lk+0][lm] = w.x; Bs[0][lk+1][lm] = w.y; Bs[0][lk+2][lm] = w.z; Bs[0][lk+3][lm] = w.w;
    }
    __syncthreads();

    float acc[4][4] = {};
    int buf = 0;

    for (int k0 = 0; k0 < DD / KS; k0 += 16) {
        float4 an, wn;
        const bool has_next = (k0 + 16) < (DD / KS);
        if (has_next) {
            an = *(const float4*)(ap + k0 + 16);
            wn = *(const float4*)(wp + k0 + 16);
        }
        #pragma unroll
        for (int k = 0; k < 16; k++) {
            float4 av = *(const float4*)&As[buf][k][ty << 2];
            float4 bv = *(const float4*)&Bs[buf][k][tx << 2];
            float am[4] = {av.x, av.y, av.z, av.w};
            float bn[4] = {bv.x, bv.y, bv.z, bv.w};
            #pragma unroll
            for (int i = 0; i < 4; i++)
                #pragma unroll
                for (int j = 0; j < 4; j++)
                    acc[i][j] = fmaf(am[i], bn[j], acc[i][j]);
        }
        if (has_next) {
            const int nb = buf ^ 1;
            As[nb][lk+0][lm] = an.x; As[nb][lk+1][lm] = an.y; As[nb][lk+2][lm] = an.z; As[nb][lk+3][lm] = an.w;
            Bs[nb][lk+0][lm] = wn.x; Bs[nb][lk+1][lm] = wn.y; Bs[nb][lk+2][lm] = wn.z; Bs[nb][lk+3][lm] = wn.w;
            __syncthreads();
            buf = nb;
        }
    }

    #pragma unroll
    for (int i = 0; i < 4; i++) {
        int row = row0 + (ty << 2) + i;
        #pragma unroll
        for (int j = 0; j < 4; j++) {
            int col = col0 + (tx << 2) + j;
            if (zm == 0) {
                g_pq2[ks][row * PP + col] = acc[i][j];
            } else {
                int b = row >> 8, jj = row & 255;
                g_pkT2[ks][(b * PP + col) * SS + jj] = acc[i][j];
            }
        }
    }
}

// ---------------------------------------------------------------------------
// Combine pkT partials: g_pkT = part0 + part1.
// ---------------------------------------------------------------------------
__global__ __launch_bounds__(256) void combine_kernel()
{
    const int i = blockIdx.x * 256 + threadIdx.x;
    const float4 a = ((const float4*)g_pkT2[0])[i];
    const float4 b = ((const float4*)g_pkT2[1])[i];
    float4 o; o.x = a.x + b.x; o.y = a.y + b.y; o.z = a.z + b.z; o.w = a.w + b.w;
    ((float4*)g_pkT)[i] = o;
}

// ---------------------------------------------------------------------------
// Phase 2a: partial scores. Block = (b, 4 query rows, p-half). 512 blocks.
//   thread t = key j:  spart[ps][i][j] = sum_{p in half} v[p]*tanh(pq+pk)
// High occupancy (~3.5 CTA/SM) hides MUFU + L2 latency.
// ---------------------------------------------------------------------------
__global__ __launch_bounds__(256) void score_kernel(
    const float* __restrict__ v)
{
    __shared__ float pq_s[TI][PP/PS];
    __shared__ float v_s[PP/PS];

    const int blk = blockIdx.x;
    const int ps = blk & 1;
    const int rest = blk >> 1;
    const int b  = rest >> 6;                 // 64 i-tiles per batch
    const int i0 = (rest & 63) * TI;
    const int t  = threadIdx.x;
    const int pbase = ps * (PP / PS);

    if (t < PP / PS) {
        v_s[t] = v[pbase + t];
        #pragma unroll
        for (int ii = 0; ii < TI; ii++) {
            const int idx = (b * SS + i0 + ii) * PP + pbase + t;
            pq_s[ii][t] = g_pq2[0][idx] + g_pq2[1][idx];
        }
    }
    __syncthreads();

    float acc[TI];
    #pragma unroll
    for (int ii = 0; ii < TI; ii++) acc[ii] = 0.f;

    const float* pkp = g_pkT + (b * PP + pbase) * SS + t;
    #pragma unroll 4
    for (int p = 0; p < PP / PS; p++) {
        float pk = pkp[p * SS];              // coalesced, L2-resident
        float vv = v_s[p];
        #pragma unroll
        for (int ii = 0; ii < TI; ii++)
            acc[ii] = fmaf(vv, fast_tanh(pq_s[ii][p] + pk), acc[ii]);
    }
    #pragma unroll
    for (int ii = 0; ii < TI; ii++)
        g_spart[ps][(b * SS + i0 + ii) * SS + t] = acc[ii];
}

// ---------------------------------------------------------------------------
// Phase 2b: softmax. 128 blocks x 256 thr; warp per query row (8 rows/block).
// ---------------------------------------------------------------------------
__global__ __launch_bounds__(256) void softmax_kernel(
    const float* __restrict__ mask,
    float* __restrict__ out_w)
{
    const int wrp = threadIdx.x >> 5, lane = threadIdx.x & 31;
    const int row = blockIdx.x * 8 + wrp;         // global query row in [0,1024)
    const int b = row >> 8;
    const float* sp0 = g_spart[0] + row * SS;
    const float* sp1 = g_spart[1] + row * SS;
    const float* mrow = mask + b * SS;

    float vals[8];
    float m = -3.4e38f;
    #pragma unroll
    for (int k = 0; k < 8; k++) {
        const int j = lane + 32 * k;
        float s = sp0[j] + sp1[j];
        s = (mrow[j] > 0.f) ? s : -1e9f;
        vals[k] = s;
        m = fmaxf(m, s);
    }
    #pragma unroll
    for (int o = 16; o > 0; o >>= 1) m = fmaxf(m, __shfl_xor_sync(0xffffffffu, m, o));
    float sum = 0.f;
    #pragma unroll
    for (int k = 0; k < 8; k++) { vals[k] = __expf(vals[k] - m); sum += vals[k]; }
    #pragma unroll
    for (int o = 16; o > 0; o >>= 1) sum += __shfl_xor_sync(0xffffffffu, sum, o);

    const float qm  = mask[row];
    const float inv = qm / sum;                   // fold query-mask into weights
    float* orow = out_w + row * SS;
    #pragma unroll
    for (int k = 0; k < 8; k++)
        orow[lane + 32 * k] = vals[k] * inv;
}

// ---------------------------------------------------------------------------
// Phase 3: attn = weights @ seq (batched GEMM), 64x64 tiles, 256 thr, 4x4,
// double-buffered. (R4-proven, 15.8us)
// ---------------------------------------------------------------------------
__global__ __launch_bounds__(256, 1) void av_kernel(
    const float* __restrict__ w,      // [B*S, S]
    const float* __restrict__ seq,    // [B, S, D]
    float* __restrict__ out_attn)     // [B*S, D]
{
    __shared__ float As[2][16][68];
    __shared__ float Bs[2][16][68];
    const int row0 = blockIdx.y * 64;
    const int col0 = blockIdx.x * 64;
    const int b = row0 >> 8;
    const int tid = threadIdx.x;
    const int tx = tid & 15, ty = tid >> 4;
    const int lm = tid >> 2;
    const int lk = (tid & 3) << 2;
    const int kb = tid >> 4;
    const int nb = (tid & 15) << 2;

    const float* ap = w + (row0 + lm) * SS + lk;
    const float* sp = seq + b * SS * DD + kb * DD + col0 + nb;

    {
        float4 a = *(const float4*)ap;
        float4 s = *(const float4*)sp;
        As[0][lk+0][lm] = a.x; As[0][lk+1][lm] = a.y; As[0][lk+2][lm] = a.z; As[0][lk+3][lm] = a.w;
        *(float4*)&Bs[0][kb][nb] = s;
    }
    __syncthreads();

    float acc[4][4] = {};
    int buf = 0;

    for (int k0 = 0; k0 < SS; k0 += 16) {
        float4 an, sn;
        const bool has_next = (k0 + 16) < SS;
        if (has_next) {
            an = *(const float4*)(ap + k0 + 16);
            sn = *(const float4*)(sp + (k0 + 16) * DD);
        }
        #pragma unroll
        for (int k = 0; k < 16; k++) {
            float4 av = *(const float4*)&As[buf][k][ty << 2];
            float4 bv = *(const float4*)&Bs[buf][k][tx << 2];
            float am[4] = {av.x, av.y, av.z, av.w};
            float bn[4] = {bv.x, bv.y, bv.z, bv.w};
            #pragma unroll
            for (int i = 0; i < 4; i++)
                #pragma unroll
                for (int j = 0; j < 4; j++)
                    acc[i][j] = fmaf(am[i], bn[j], acc[i][j]);
        }
        if (has_next) {
            const int nbuf = buf ^ 1;
            As[nbuf][lk+0][lm] = an.x; As[nbuf][lk+1][lm] = an.y; As[nbuf][lk+2][lm] = an.z; As[nbuf][lk+3][lm] = an.w;
            *(float4*)&Bs[nbuf][kb][nb] = sn;
            __syncthreads();
            buf = nbuf;
        }
    }

    #pragma unroll
    for (int i = 0; i < 4; i++) {
        float* orow = out_attn + (row0 + (ty << 2) + i) * DD + col0 + (tx << 2);
        #pragma unroll
        for (int j = 0; j < 4; j++) orow[j] = acc[i][j];
    }
}

extern "C" void kernel_launch(void* const* d_in, const int* in_sizes, int n_in,
                              void* d_out, int out_size)
{
    const float* seq  = (const float*)d_in[0];
    const float* mask = (const float*)d_in[1];
    const float* W1   = (const float*)d_in[2];
    const float* W2   = (const float*)d_in[3];
    const float* v    = (const float*)d_in[4];
    float* out_attn = (float*)d_out;                    // [B,S,D]
    float* out_w    = (float*)d_out + BB * SS * DD;     // [B,S,S]

    dim3 g1(PP / 64, (BB * SS) / 64, 2 * KS);
    proj_kernel<<<g1, 256>>>(seq, W1, W2);
    combine_kernel<<<(BB * PP * SS / 4) / 256, 256>>>();
    score_kernel<<<(BB * SS / TI) * PS, 256>>>(v);
    softmax_kernel<<<(BB * SS) / 8, 256>>>(mask, out_w);
    dim3 g3(DD / 64, (BB * SS) / 64);
    av_kernel<<<g3, 256>>>(out_w, seq, out_attn);
}